// round 4
// baseline (speedup 1.0000x reference)
#include <cuda_runtime.h>

// Problem constants (match reference_code)
#define N_USERS 200000
#define N_ITEMS 100000
#define N_NODES (N_USERS + N_ITEMS)    // 300000
#define N_EDGES 4800000                // % 128 == 0
#define EMB 64
#define BATCH 4096
#define NSEL (2 * BATCH)               // 8192 selected output rows
#define BITWORDS ((N_NODES + 31) / 32) // 9375 words = 37.5KB
#define CAP 128                        // bin capacity per slot (Poisson(16) -> safe)

// Scratch (allocation-free: __device__ globals)
__device__ int      g_slot[N_NODES];      // node -> representative output slot
__device__ int      g_rep[NSEL];          // output row -> representative slot
__device__ unsigned g_bitmap[BITWORDS];   // selected-node membership (per call)
__device__ int      g_cnt[NSEL];          // edges binned per slot (per call)
__device__ int2     g_bin[NSEL * CAP];    // (col, val-as-int) per slot, 8MB
__device__ float    g_acc[NSEL * EMB];    // per-slot A*x0 row (plain stores)

// ---------------------------------------------------------------------------
// Kernel 1: zero bitmap + counters (graph replays -> re-zero each call).
// g_acc needs NO zeroing: k_accum writes every rep row with plain stores and
// non-rep rows are never read.
// ---------------------------------------------------------------------------
__global__ void k_init() {
    int i = blockIdx.x * blockDim.x + threadIdx.x;
    int stride = gridDim.x * blockDim.x;
    for (int t = i; t < BITWORDS; t += stride) g_bitmap[t] = 0u;
    for (int t = i; t < NSEL; t += stride)     g_cnt[t] = 0;
}

// ---------------------------------------------------------------------------
// Kernel 2: node->slot map + membership bitmap. Duplicate ids: plain-write
// race picks ONE representative; any winner is correct (acc[rep] = full sum).
// ---------------------------------------------------------------------------
__global__ void k_build(const int* __restrict__ user_id,
                        const int* __restrict__ item_id) {
    int i = blockIdx.x * blockDim.x + threadIdx.x;
    if (i >= NSEL) return;
    int node = (i < BATCH) ? user_id[i] : (N_USERS + item_id[i - BATCH]);
    g_slot[node] = i;
    atomicOr(&g_bitmap[node >> 5], 1u << (node & 31));
}

// ---------------------------------------------------------------------------
// Kernel 3: resolve each output row's representative slot (after k_build's
// race has settled at the kernel boundary). Shortens k_out's load chain.
// ---------------------------------------------------------------------------
__global__ void k_rep(const int* __restrict__ user_id,
                      const int* __restrict__ item_id) {
    int i = blockIdx.x * blockDim.x + threadIdx.x;
    if (i >= NSEL) return;
    int node = (i < BATCH) ? user_id[i] : (N_USERS + item_id[i - BATCH]);
    g_rep[i] = g_slot[node];
}

// ---------------------------------------------------------------------------
// Kernel 4: scan edges, bin hits by slot. Pure stream + SMEM bitmap test;
// hit lanes (~2.7%) independently claim a bin position. No float atomics.
// ---------------------------------------------------------------------------
__global__ void __launch_bounds__(256)
k_scan(const int4*  __restrict__ adj_row4,
       const int*   __restrict__ adj_col,
       const float* __restrict__ adj_vals) {
    __shared__ unsigned sbm[BITWORDS];
    for (int t = threadIdx.x; t < BITWORDS; t += blockDim.x)
        sbm[t] = g_bitmap[t];
    __syncthreads();

    const int tid     = blockIdx.x * blockDim.x + threadIdx.x;
    const int nthread = gridDim.x * blockDim.x;
    const int nvec    = N_EDGES / 4;          // 1.2M int4 loads, exact

    for (int i = tid; i < nvec; i += nthread) {
        int4 r4 = adj_row4[i];
        #pragma unroll
        for (int k = 0; k < 4; k++) {
            int r = (k == 0) ? r4.x : (k == 1) ? r4.y : (k == 2) ? r4.z : r4.w;
            if ((sbm[r >> 5] >> (r & 31)) & 1u) {
                int e = i * 4 + k;
                int s = g_slot[r];
                int pos = atomicAdd(&g_cnt[s], 1);
                if (pos < CAP) {
                    g_bin[s * CAP + pos] =
                        make_int2(adj_col[e], __float_as_int(adj_vals[e]));
                }
            }
        }
    }
}

// ---------------------------------------------------------------------------
// Kernel 5: one warp per slot; accumulate its bin in registers (float2/lane),
// gathers batched x4 for MLP, single plain store. Zero atomics.
// ---------------------------------------------------------------------------
__global__ void __launch_bounds__(256)
k_accum(const float* __restrict__ user_emb,
        const float* __restrict__ item_emb) {
    const int warp = (blockIdx.x * blockDim.x + threadIdx.x) >> 5;
    const int lane = threadIdx.x & 31;
    if (warp >= NSEL) return;

    int cnt = g_cnt[warp];
    if (cnt > CAP) cnt = CAP;
    const int2* bin = g_bin + warp * CAP;

    float2 acc = make_float2(0.f, 0.f);
    for (int j0 = 0; j0 < cnt; j0 += 4) {
        int2 e[4];
        #pragma unroll
        for (int t = 0; t < 4; t++)
            e[t] = (j0 + t < cnt) ? bin[j0 + t] : make_int2(0, 0); // v=0 pad
        #pragma unroll
        for (int t = 0; t < 4; t++) {
            int   c = e[t].x;
            float v = __int_as_float(e[t].y);
            const float2* xp = (c < N_USERS)
                ? (const float2*)(user_emb + (size_t)c * EMB)
                : (const float2*)(item_emb + (size_t)(c - N_USERS) * EMB);
            float2 x = xp[lane];          // lane covers elems {2l, 2l+1}
            acc.x += v * x.x;
            acc.y += v * x.y;
        }
    }
    ((float2*)(g_acc + (size_t)warp * EMB))[lane] = acc;
}

// ---------------------------------------------------------------------------
// Kernel 6: out[i][:] = 2*x0[node_i][:] + acc[rep_i][:], float4-wide.
// Chain is now g_rep (L2-hot) -> g_acc (L2-hot, just written).
// ---------------------------------------------------------------------------
__global__ void k_out(const float* __restrict__ user_emb,
                      const float* __restrict__ item_emb,
                      const int* __restrict__ user_id,
                      const int* __restrict__ item_id,
                      float4* __restrict__ out4) {
    int idx = blockIdx.x * blockDim.x + threadIdx.x;
    if (idx >= NSEL * 16) return;
    int i = idx >> 4;        // output row
    int q = idx & 15;        // float4 index within row
    const float4* x4;
    if (i < BATCH) {
        x4 = (const float4*)(user_emb + (size_t)user_id[i] * EMB);
    } else {
        x4 = (const float4*)(item_emb + (size_t)item_id[i - BATCH] * EMB);
    }
    int rep = g_rep[i];
    float4 x = x4[q];
    float4 a = ((const float4*)g_acc)[rep * 16 + q];
    out4[idx] = make_float4(2.0f * x.x + a.x, 2.0f * x.y + a.y,
                            2.0f * x.z + a.z, 2.0f * x.w + a.w);
}

// ---------------------------------------------------------------------------
// Inputs (metadata order): user_emb, item_emb, adj_row, adj_col, adj_vals,
//                          user_id, item_id. Output: 8192x64 float32.
// ---------------------------------------------------------------------------
extern "C" void kernel_launch(void* const* d_in, const int* in_sizes, int n_in,
                              void* d_out, int out_size) {
    const float* user_emb = (const float*)d_in[0];
    const float* item_emb = (const float*)d_in[1];
    const int4*  adj_row4 = (const int4*)d_in[2];
    const int*   adj_col  = (const int*)d_in[3];
    const float* adj_vals = (const float*)d_in[4];
    const int*   user_id  = (const int*)d_in[5];
    const int*   item_id  = (const int*)d_in[6];
    float4*      out4     = (float4*)d_out;

    k_init <<<64, 256>>>();
    k_build<<<(NSEL + 255) / 256, 256>>>(user_id, item_id);
    k_rep  <<<(NSEL + 255) / 256, 256>>>(user_id, item_id);
    k_scan <<<444, 256>>>(adj_row4, adj_col, adj_vals);
    k_accum<<<(NSEL * 32 + 255) / 256, 256>>>(user_emb, item_emb);
    k_out  <<<(NSEL * 16 + 255) / 256, 256>>>(user_emb, item_emb,
                                              user_id, item_id, out4);
}

// round 6
// speedup vs baseline: 1.3904x; 1.3904x over previous
#include <cuda_runtime.h>

// Problem constants (match reference_code)
#define N_USERS 200000
#define N_ITEMS 100000
#define N_NODES (N_USERS + N_ITEMS)    // 300000
#define N_EDGES 4800000                // % 4 == 0
#define EMB 64
#define BATCH 4096
#define NSEL (2 * BATCH)               // 8192 selected output rows
#define BITWORDS ((N_NODES + 31) / 32) // 9375
#define BITWORDS_PAD 9376              // multiple of 4 for int4 copies (37.5KB)
#define CAP 128                        // bin capacity/slot (Poisson(16) -> safe)

// Scratch (allocation-free: __device__ globals)
__device__ int      g_slot[N_NODES];             // node -> representative slot
__device__ int      g_rep[NSEL];                 // output row -> rep slot
__device__ __align__(16) unsigned g_bitmap[BITWORDS_PAD];
__device__ int      g_cnt[NSEL];                 // per-slot bin counts
__device__ int2     g_bin[NSEL * CAP];           // (col, val bits), 8MB
__device__ float    g_acc[NSEL * EMB];           // per-slot A*x0 row

// ---------------------------------------------------------------------------
// Kernel 1: zero bitmap + counters (graph replays -> re-zero each call).
// ---------------------------------------------------------------------------
__global__ void k_init() {
    int i = blockIdx.x * blockDim.x + threadIdx.x;
    int stride = gridDim.x * blockDim.x;
    for (int t = i; t < BITWORDS_PAD; t += stride) g_bitmap[t] = 0u;
    for (int t = i; t < NSEL; t += stride)         g_cnt[t] = 0;
}

// ---------------------------------------------------------------------------
// Kernel 2: node->slot + membership bitmap. Duplicate ids: plain-write race
// picks ONE representative; any winner is correct (acc[rep] = full sum).
// ---------------------------------------------------------------------------
__global__ void k_build(const int* __restrict__ user_id,
                        const int* __restrict__ item_id) {
    int i = blockIdx.x * blockDim.x + threadIdx.x;
    if (i >= NSEL) return;
    int node = (i < BATCH) ? user_id[i] : (N_USERS + item_id[i - BATCH]);
    g_slot[node] = i;
    atomicOr(&g_bitmap[node >> 5], 1u << (node & 31));
}

// ---------------------------------------------------------------------------
// Kernel 3: resolve each output row's representative slot (race settled at
// the kernel boundary). Shortens k_out's load chain.
// ---------------------------------------------------------------------------
__global__ void k_rep(const int* __restrict__ user_id,
                      const int* __restrict__ item_id) {
    int i = blockIdx.x * blockDim.x + threadIdx.x;
    if (i >= NSEL) return;
    int node = (i < BATCH) ? user_id[i] : (N_USERS + item_id[i - BATCH]);
    g_rep[i] = g_slot[node];
}

// ---------------------------------------------------------------------------
// Kernel 4: scan edges, bin hits by slot.
// 512 thr/block, 4 blocks/SM (regs capped at 32), grid 592 -> ~100% occ.
// Two int4 row-loads in flight per iteration (2 loop iterations total).
// ---------------------------------------------------------------------------
__device__ __forceinline__ void scan_one(int r, int e,
                                         const unsigned* sbm,
                                         const int*   __restrict__ adj_col,
                                         const float* __restrict__ adj_vals) {
    if ((sbm[r >> 5] >> (r & 31)) & 1u) {
        int   c = adj_col[e];           // independent loads first
        float v = adj_vals[e];
        int   s = g_slot[r];
        int pos = atomicAdd(&g_cnt[s], 1);
        if (pos < CAP)
            g_bin[s * CAP + pos] = make_int2(c, __float_as_int(v));
    }
}

__global__ void __launch_bounds__(512, 4)
k_scan(const int4*  __restrict__ adj_row4,
       const int*   __restrict__ adj_col,
       const float* __restrict__ adj_vals) {
    __shared__ __align__(16) unsigned sbm[BITWORDS_PAD];
    {
        const uint4* src = (const uint4*)g_bitmap;
        uint4*       dst = (uint4*)sbm;
        for (int t = threadIdx.x; t < BITWORDS_PAD / 4; t += 512)
            dst[t] = src[t];
    }
    __syncthreads();

    const int tid     = blockIdx.x * 512 + threadIdx.x;
    const int nthread = gridDim.x * 512;
    const int nvec    = N_EDGES / 4;     // 1.2M int4 elements

    for (int i = tid; i < nvec; i += 2 * nthread) {
        int  j    = i + nthread;
        bool hasb = (j < nvec);
        int4 a = adj_row4[i];
        int4 b = hasb ? adj_row4[j] : make_int4(0, 0, 0, 0);

        scan_one(a.x, 4 * i,     sbm, adj_col, adj_vals);
        scan_one(a.y, 4 * i + 1, sbm, adj_col, adj_vals);
        scan_one(a.z, 4 * i + 2, sbm, adj_col, adj_vals);
        scan_one(a.w, 4 * i + 3, sbm, adj_col, adj_vals);
        if (hasb) {
            scan_one(b.x, 4 * j,     sbm, adj_col, adj_vals);
            scan_one(b.y, 4 * j + 1, sbm, adj_col, adj_vals);
            scan_one(b.z, 4 * j + 2, sbm, adj_col, adj_vals);
            scan_one(b.w, 4 * j + 3, sbm, adj_col, adj_vals);
        }
    }
}

// ---------------------------------------------------------------------------
// Kernel 5: one warp per slot; accumulate bin in registers (float2/lane),
// 8 gathers in flight, single plain store. Zero atomics.
// ---------------------------------------------------------------------------
__global__ void __launch_bounds__(256)
k_accum(const float* __restrict__ user_emb,
        const float* __restrict__ item_emb) {
    const int warp = (blockIdx.x * blockDim.x + threadIdx.x) >> 5;
    const int lane = threadIdx.x & 31;
    if (warp >= NSEL) return;

    int cnt = g_cnt[warp];
    if (cnt > CAP) cnt = CAP;
    const int2* bin = g_bin + warp * CAP;

    float2 acc = make_float2(0.f, 0.f);
    for (int j0 = 0; j0 < cnt; j0 += 8) {
        int2 e[8];
        #pragma unroll
        for (int t = 0; t < 8; t++)
            e[t] = (j0 + t < cnt) ? bin[j0 + t] : make_int2(0, 0); // v=0 pad
        float2 x[8];
        #pragma unroll
        for (int t = 0; t < 8; t++) {
            int c = e[t].x;
            const float2* xp = (c < N_USERS)
                ? (const float2*)(user_emb + (size_t)c * EMB)
                : (const float2*)(item_emb + (size_t)(c - N_USERS) * EMB);
            x[t] = xp[lane];              // lane covers elems {2l, 2l+1}
        }
        #pragma unroll
        for (int t = 0; t < 8; t++) {
            float v = __int_as_float(e[t].y);
            acc.x += v * x[t].x;
            acc.y += v * x[t].y;
        }
    }
    ((float2*)(g_acc + (size_t)warp * EMB))[lane] = acc;
}

// ---------------------------------------------------------------------------
// Kernel 6: out[i][:] = 2*x0[node_i][:] + acc[rep_i][:], float4-wide.
// ---------------------------------------------------------------------------
__global__ void k_out(const float* __restrict__ user_emb,
                      const float* __restrict__ item_emb,
                      const int* __restrict__ user_id,
                      const int* __restrict__ item_id,
                      float4* __restrict__ out4) {
    int idx = blockIdx.x * blockDim.x + threadIdx.x;
    if (idx >= NSEL * 16) return;
    int i = idx >> 4;        // output row
    int q = idx & 15;        // float4 index within row
    const float4* x4;
    if (i < BATCH) {
        x4 = (const float4*)(user_emb + (size_t)user_id[i] * EMB);
    } else {
        x4 = (const float4*)(item_emb + (size_t)item_id[i - BATCH] * EMB);
    }
    int rep = g_rep[i];
    float4 x = x4[q];
    float4 a = ((const float4*)g_acc)[rep * 16 + q];
    out4[idx] = make_float4(2.0f * x.x + a.x, 2.0f * x.y + a.y,
                            2.0f * x.z + a.z, 2.0f * x.w + a.w);
}

// ---------------------------------------------------------------------------
// Inputs (metadata order): user_emb, item_emb, adj_row, adj_col, adj_vals,
//                          user_id, item_id. Output: 8192x64 float32.
// ---------------------------------------------------------------------------
extern "C" void kernel_launch(void* const* d_in, const int* in_sizes, int n_in,
                              void* d_out, int out_size) {
    const float* user_emb = (const float*)d_in[0];
    const float* item_emb = (const float*)d_in[1];
    const int4*  adj_row4 = (const int4*)d_in[2];
    const int*   adj_col  = (const int*)d_in[3];
    const float* adj_vals = (const float*)d_in[4];
    const int*   user_id  = (const int*)d_in[5];
    const int*   item_id  = (const int*)d_in[6];
    float4*      out4     = (float4*)d_out;

    k_init <<<64, 256>>>();
    k_build<<<(NSEL + 255) / 256, 256>>>(user_id, item_id);
    k_rep  <<<(NSEL + 255) / 256, 256>>>(user_id, item_id);
    k_scan <<<592, 512>>>(adj_row4, adj_col, adj_vals);
    k_accum<<<(NSEL * 32 + 255) / 256, 256>>>(user_emb, item_emb);
    k_out  <<<(NSEL * 16 + 255) / 256, 256>>>(user_emb, item_emb,
                                              user_id, item_id, out4);
}

// round 7
// speedup vs baseline: 1.6864x; 1.2129x over previous
#include <cuda_runtime.h>

// Problem constants (match reference_code)
#define N_USERS 200000
#define N_ITEMS 100000
#define N_NODES (N_USERS + N_ITEMS)    // 300000
#define N_EDGES 4800000
#define EMB 64
#define BATCH 4096
#define NSEL (2 * BATCH)               // 8192 selected output rows
#define BITWORDS ((N_NODES + 31) / 32) // 9375
#define BITWORDS_PAD 9376              // multiple of 4 (37.5KB)
#define CAP 128                        // bin capacity/slot (Poisson(16))
#define NVEC (N_EDGES / 4)             // 1,200,000 int4 vectors
#define QCAP 2048                      // per-block hit queue (mean ~295)
#define SCAN_BLOCKS 444                // 3 resident blocks x 148 SMs
#define VPT 6                          // int4 vectors per thread (MLP)

// Scratch (allocation-free: __device__ globals)
__device__ int      g_slot[N_NODES];             // node -> representative slot
__device__ int      g_rep[NSEL];                 // output row -> rep slot
__device__ __align__(16) unsigned g_bitmap[BITWORDS_PAD];
__device__ int      g_cnt[NSEL];                 // per-slot bin counts
__device__ int2     g_bin[NSEL * CAP];           // (col, val bits), 8MB
__device__ float    g_acc[NSEL * EMB];           // per-slot A*x0 row

// ---------------------------------------------------------------------------
// Kernel 1: zero the membership bitmap (graph replays -> re-zero each call).
// ---------------------------------------------------------------------------
__global__ void k_init() {
    int i = blockIdx.x * blockDim.x + threadIdx.x;
    int stride = gridDim.x * blockDim.x;
    for (int t = i; t < BITWORDS_PAD; t += stride) g_bitmap[t] = 0u;
}

// ---------------------------------------------------------------------------
// Kernel 2: node->slot map + bitmap + zero this slot's bin counter.
// Duplicate ids: plain-write race picks ONE representative; any winner is
// correct (acc[rep] holds the full segment sum for that node).
// ---------------------------------------------------------------------------
__global__ void k_build(const int* __restrict__ user_id,
                        const int* __restrict__ item_id) {
    int i = blockIdx.x * blockDim.x + threadIdx.x;
    if (i >= NSEL) return;
    int node = (i < BATCH) ? user_id[i] : (N_USERS + item_id[i - BATCH]);
    g_slot[node] = i;
    g_cnt[i] = 0;
    atomicOr(&g_bitmap[node >> 5], 1u << (node & 31));
}

// ---------------------------------------------------------------------------
// Kernel 3: scan edges -> per-block SMEM hit queue -> dense drain into bins.
// Main loop is pure streaming (LDG.128 row stream + SMEM bitmap test + rare
// ATOMS push). All global latency chains happen once, in the drain phase.
// Prologue also resolves g_rep (merged former k_rep kernel).
// ---------------------------------------------------------------------------
__global__ void __launch_bounds__(512, 3)
k_scan(const int4*  __restrict__ adj_row4,
       const int*   __restrict__ adj_col,
       const float* __restrict__ adj_vals,
       const int*   __restrict__ user_id,
       const int*   __restrict__ item_id) {
    __shared__ __align__(16) unsigned sbm[BITWORDS_PAD];
    __shared__ int2 q[QCAP];
    __shared__ int  qn;

    const int tid = blockIdx.x * 512 + threadIdx.x;

    // merged k_rep: one entry per thread across the first 16 blocks
    if (tid < NSEL) {
        int node = (tid < BATCH) ? user_id[tid]
                                 : (N_USERS + item_id[tid - BATCH]);
        g_rep[tid] = g_slot[node];
    }

    if (threadIdx.x == 0) qn = 0;
    {
        const uint4* src = (const uint4*)g_bitmap;
        uint4*       dst = (uint4*)sbm;
        for (int t = threadIdx.x; t < BITWORDS_PAD / 4; t += 512)
            dst[t] = src[t];
    }
    __syncthreads();

    const int nthread = SCAN_BLOCKS * 512;   // 227,328

    // Load up to VPT int4 row-vectors upfront (MLP), then test 4*VPT edges.
    int4 r[VPT];
    #pragma unroll
    for (int t = 0; t < VPT; t++) {
        int i = tid + t * nthread;
        if (i < NVEC) r[t] = adj_row4[i];
    }
    #pragma unroll
    for (int t = 0; t < VPT; t++) {
        int i = tid + t * nthread;
        if (i >= NVEC) break;
        int rv[4] = {r[t].x, r[t].y, r[t].z, r[t].w};
        #pragma unroll
        for (int k = 0; k < 4; k++) {
            int rn = rv[k];
            if ((sbm[rn >> 5] >> (rn & 31)) & 1u) {
                int e = 4 * i + k;
                int p = atomicAdd(&qn, 1);          // ATOMS, rare
                if (p < QCAP) {
                    q[p] = make_int2(e, rn);
                } else {                            // statistically impossible
                    int s = g_slot[rn];
                    int pos = atomicAdd(&g_cnt[s], 1);
                    if (pos < CAP)
                        g_bin[s * CAP + pos] =
                            make_int2(adj_col[e], __float_as_int(adj_vals[e]));
                }
            }
        }
    }
    __syncthreads();

    // Dense drain: ~295 entries over 512 threads; all loads independent.
    int n = qn < QCAP ? qn : QCAP;
    for (int t = threadIdx.x; t < n; t += 512) {
        int2 er = q[t];
        int   c = adj_col[er.x];
        float v = adj_vals[er.x];
        int   s = g_slot[er.y];
        int pos = atomicAdd(&g_cnt[s], 1);
        if (pos < CAP)
            g_bin[s * CAP + pos] = make_int2(c, __float_as_int(v));
    }
}

// ---------------------------------------------------------------------------
// Kernel 4: one warp per slot; accumulate bin in registers (float2/lane),
// 8 gathers in flight, single plain store. Zero atomics.
// ---------------------------------------------------------------------------
__global__ void __launch_bounds__(256)
k_accum(const float* __restrict__ user_emb,
        const float* __restrict__ item_emb) {
    const int warp = (blockIdx.x * blockDim.x + threadIdx.x) >> 5;
    const int lane = threadIdx.x & 31;
    if (warp >= NSEL) return;

    int cnt = g_cnt[warp];
    if (cnt > CAP) cnt = CAP;
    const int2* bin = g_bin + warp * CAP;

    float2 acc = make_float2(0.f, 0.f);
    for (int j0 = 0; j0 < cnt; j0 += 8) {
        int2 e[8];
        #pragma unroll
        for (int t = 0; t < 8; t++)
            e[t] = (j0 + t < cnt) ? bin[j0 + t] : make_int2(0, 0); // v=0 pad
        float2 x[8];
        #pragma unroll
        for (int t = 0; t < 8; t++) {
            int c = e[t].x;
            const float2* xp = (c < N_USERS)
                ? (const float2*)(user_emb + (size_t)c * EMB)
                : (const float2*)(item_emb + (size_t)(c - N_USERS) * EMB);
            x[t] = xp[lane];              // lane covers elems {2l, 2l+1}
        }
        #pragma unroll
        for (int t = 0; t < 8; t++) {
            float v = __int_as_float(e[t].y);
            acc.x += v * x[t].x;
            acc.y += v * x[t].y;
        }
    }
    ((float2*)(g_acc + (size_t)warp * EMB))[lane] = acc;
}

// ---------------------------------------------------------------------------
// Kernel 5: out[i][:] = 2*x0[node_i][:] + acc[rep_i][:], float4-wide.
// ---------------------------------------------------------------------------
__global__ void k_out(const float* __restrict__ user_emb,
                      const float* __restrict__ item_emb,
                      const int* __restrict__ user_id,
                      const int* __restrict__ item_id,
                      float4* __restrict__ out4) {
    int idx = blockIdx.x * blockDim.x + threadIdx.x;
    if (idx >= NSEL * 16) return;
    int i = idx >> 4;        // output row
    int q = idx & 15;        // float4 index within row
    const float4* x4;
    if (i < BATCH) {
        x4 = (const float4*)(user_emb + (size_t)user_id[i] * EMB);
    } else {
        x4 = (const float4*)(item_emb + (size_t)item_id[i - BATCH] * EMB);
    }
    int rep = g_rep[i];
    float4 x = x4[q];
    float4 a = ((const float4*)g_acc)[rep * 16 + q];
    out4[idx] = make_float4(2.0f * x.x + a.x, 2.0f * x.y + a.y,
                            2.0f * x.z + a.z, 2.0f * x.w + a.w);
}

// ---------------------------------------------------------------------------
// Inputs (metadata order): user_emb, item_emb, adj_row, adj_col, adj_vals,
//                          user_id, item_id. Output: 8192x64 float32.
// ---------------------------------------------------------------------------
extern "C" void kernel_launch(void* const* d_in, const int* in_sizes, int n_in,
                              void* d_out, int out_size) {
    const float* user_emb = (const float*)d_in[0];
    const float* item_emb = (const float*)d_in[1];
    const int4*  adj_row4 = (const int4*)d_in[2];
    const int*   adj_col  = (const int*)d_in[3];
    const float* adj_vals = (const float*)d_in[4];
    const int*   user_id  = (const int*)d_in[5];
    const int*   item_id  = (const int*)d_in[6];
    float4*      out4     = (float4*)d_out;

    k_init <<<64, 256>>>();
    k_build<<<(NSEL + 255) / 256, 256>>>(user_id, item_id);
    k_scan <<<SCAN_BLOCKS, 512>>>(adj_row4, adj_col, adj_vals,
                                  user_id, item_id);
    k_accum<<<(NSEL * 32 + 255) / 256, 256>>>(user_emb, item_emb);
    k_out  <<<(NSEL * 16 + 255) / 256, 256>>>(user_emb, item_emb,
                                              user_id, item_id, out4);
}

// round 8
// speedup vs baseline: 1.9151x; 1.1356x over previous
#include <cuda_runtime.h>

// Problem constants (match reference_code)
#define N_USERS 200000
#define N_ITEMS 100000
#define N_NODES (N_USERS + N_ITEMS)    // 300000
#define N_EDGES 4800000
#define EMB 64
#define BATCH 4096
#define NSEL (2 * BATCH)               // 8192 selected output rows
#define BITWORDS ((N_NODES + 31) / 32) // 9375
#define BITWORDS_PAD 9376              // multiple of 4 (37.5KB)
#define CAP 128                        // bin capacity/slot (Poisson(16))
#define NVEC (N_EDGES / 4)             // 1,200,000 int4 vectors
#define QCAP 2048                      // per-block hit queue (mean ~295)
#define SCAN_BLOCKS 444                // 3 resident blocks x 148 SMs
#define VPT 6                          // int4 vectors per thread (MLP)

// Scratch (allocation-free: __device__ globals)
__device__ int      g_slot[N_NODES];             // node -> representative slot
__device__ int      g_rep[NSEL];                 // output row -> rep slot
__device__ __align__(16) unsigned g_bitmap[BITWORDS_PAD];
__device__ int      g_cnt[NSEL];                 // per-slot bin counts
__device__ __align__(16) int2 g_bin[NSEL * CAP]; // (col, val bits), 8MB
                                                 // NOTE: only ever holds valid
                                                 // cols (zero-init / written
                                                 // with real edges) -> stale
                                                 // entries are safe to gather.

// ---------------------------------------------------------------------------
// Kernel 1: zero the membership bitmap (graph replays -> re-zero each call).
// ---------------------------------------------------------------------------
__global__ void k_init() {
    int i = blockIdx.x * blockDim.x + threadIdx.x;
    int stride = gridDim.x * blockDim.x;
    for (int t = i; t < BITWORDS_PAD; t += stride) g_bitmap[t] = 0u;
}

// ---------------------------------------------------------------------------
// Kernel 2: node->slot map + bitmap + zero this slot's bin counter.
// Duplicate ids: plain-write race picks ONE representative; any winner is
// correct (its bin holds the full edge set for that node).
// ---------------------------------------------------------------------------
__global__ void k_build(const int* __restrict__ user_id,
                        const int* __restrict__ item_id) {
    int i = blockIdx.x * blockDim.x + threadIdx.x;
    if (i >= NSEL) return;
    int node = (i < BATCH) ? user_id[i] : (N_USERS + item_id[i - BATCH]);
    g_slot[node] = i;
    g_cnt[i] = 0;
    atomicOr(&g_bitmap[node >> 5], 1u << (node & 31));
}

// ---------------------------------------------------------------------------
// Kernel 3: scan edges -> per-block SMEM hit queue -> dense drain into bins.
// Prologue also resolves g_rep (merged k_rep).
// ---------------------------------------------------------------------------
__global__ void __launch_bounds__(512, 3)
k_scan(const int4*  __restrict__ adj_row4,
       const int*   __restrict__ adj_col,
       const float* __restrict__ adj_vals,
       const int*   __restrict__ user_id,
       const int*   __restrict__ item_id) {
    __shared__ __align__(16) unsigned sbm[BITWORDS_PAD];
    __shared__ int2 q[QCAP];
    __shared__ int  qn;

    const int tid = blockIdx.x * 512 + threadIdx.x;

    // merged k_rep: one entry per thread across the first 16 blocks
    if (tid < NSEL) {
        int node = (tid < BATCH) ? user_id[tid]
                                 : (N_USERS + item_id[tid - BATCH]);
        g_rep[tid] = g_slot[node];
    }

    if (threadIdx.x == 0) qn = 0;
    {
        const uint4* src = (const uint4*)g_bitmap;
        uint4*       dst = (uint4*)sbm;
        for (int t = threadIdx.x; t < BITWORDS_PAD / 4; t += 512)
            dst[t] = src[t];
    }
    __syncthreads();

    const int nthread = SCAN_BLOCKS * 512;   // 227,328

    int4 r[VPT];
    #pragma unroll
    for (int t = 0; t < VPT; t++) {
        int i = tid + t * nthread;
        if (i < NVEC) r[t] = adj_row4[i];
    }
    #pragma unroll
    for (int t = 0; t < VPT; t++) {
        int i = tid + t * nthread;
        if (i >= NVEC) break;
        int rv[4] = {r[t].x, r[t].y, r[t].z, r[t].w};
        #pragma unroll
        for (int k = 0; k < 4; k++) {
            int rn = rv[k];
            if ((sbm[rn >> 5] >> (rn & 31)) & 1u) {
                int e = 4 * i + k;
                int p = atomicAdd(&qn, 1);          // ATOMS, rare
                if (p < QCAP) {
                    q[p] = make_int2(e, rn);
                } else {                            // statistically impossible
                    int s = g_slot[rn];
                    int pos = atomicAdd(&g_cnt[s], 1);
                    if (pos < CAP)
                        g_bin[s * CAP + pos] =
                            make_int2(adj_col[e], __float_as_int(adj_vals[e]));
                }
            }
        }
    }
    __syncthreads();

    int n = qn < QCAP ? qn : QCAP;
    for (int t = threadIdx.x; t < n; t += 512) {
        int2 er = q[t];
        int   c = adj_col[er.x];
        float v = adj_vals[er.x];
        int   s = g_slot[er.y];
        int pos = atomicAdd(&g_cnt[s], 1);
        if (pos < CAP)
            g_bin[s * CAP + pos] = make_int2(c, __float_as_int(v));
    }
}

// ---------------------------------------------------------------------------
// Kernel 4 (fused accum + out): one warp per OUTPUT ROW.
//  - speculative preload of first 16 bin entries || cnt || x0 row
//  - 16-lane halves each process one edge (float4/lane), 4 edges in flight
//    per half per batch of 8 entries
//  - halves combined via shfl_xor(16); lanes 0-15 store out float4.
// ---------------------------------------------------------------------------
__device__ __forceinline__ const float4* emb_row(int c,
                                                 const float* __restrict__ ue,
                                                 const float* __restrict__ ie) {
    return (c < N_USERS)
        ? (const float4*)(ue + (size_t)c * EMB)
        : (const float4*)(ie + (size_t)(c - N_USERS) * EMB);
}

__global__ void __launch_bounds__(256)
k_accum_out(const float* __restrict__ user_emb,
            const float* __restrict__ item_emb,
            const int*   __restrict__ user_id,
            const int*   __restrict__ item_id,
            float4*      __restrict__ out4) {
    const int row  = (blockIdx.x * blockDim.x + threadIdx.x) >> 5;
    const int lane = threadIdx.x & 31;
    if (row >= NSEL) return;
    const int half = lane >> 4;     // which edge of a pair
    const int l16  = lane & 15;     // float4 index within emb row

    // Level 1: independent loads
    int rep = g_rep[row];
    int id  = (row < BATCH) ? user_id[row] : item_id[row - BATCH];

    // Level 2: all independent — cnt, 16 speculative bin entries, x0 row
    const int4* bin4 = (const int4*)(g_bin + rep * CAP); // 2 entries per int4
    int4 eb[8];
    #pragma unroll
    for (int t = 0; t < 8; t++) eb[t] = bin4[t];
    int cnt = g_cnt[rep];
    if (cnt > CAP) cnt = CAP;
    const float4* x0p = (row < BATCH)
        ? (const float4*)(user_emb + (size_t)id * EMB)
        : (const float4*)(item_emb + (size_t)id * EMB);
    float4 x0 = x0p[l16];

    float4 acc = make_float4(0.f, 0.f, 0.f, 0.f);

    // process one batch of 8 entries: this half takes entries j0+2t+half
    auto process = [&](const int4* b, int j0) {
        float4 x[4];
        float  v[4];
        #pragma unroll
        for (int t = 0; t < 4; t++) {
            int j = j0 + 2 * t + half;
            int   c  = half ? b[t].z : b[t].x;
            int   vb = half ? b[t].w : b[t].y;
            bool ok = (j < cnt);
            v[t] = ok ? __int_as_float(vb) : 0.0f;
            // stale cols are valid node ids -> safe gather even when !ok
            x[t] = emb_row(c, user_emb, item_emb)[l16];
        }
        #pragma unroll
        for (int t = 0; t < 4; t++) {
            acc.x += v[t] * x[t].x;
            acc.y += v[t] * x[t].y;
            acc.z += v[t] * x[t].z;
            acc.w += v[t] * x[t].w;
        }
    };

    if (cnt > 0)  process(eb,     0);
    if (cnt > 8)  process(eb + 4, 8);
    for (int j0 = 16; j0 < cnt; j0 += 8) {
        int4 b[4];
        #pragma unroll
        for (int t = 0; t < 4; t++) b[t] = bin4[j0 / 2 + t];
        process(b, j0);
    }

    // combine the two halves (lane l and l^16 cover the same emb elems)
    acc.x += __shfl_xor_sync(0xffffffffu, acc.x, 16);
    acc.y += __shfl_xor_sync(0xffffffffu, acc.y, 16);
    acc.z += __shfl_xor_sync(0xffffffffu, acc.z, 16);
    acc.w += __shfl_xor_sync(0xffffffffu, acc.w, 16);

    if (half == 0) {
        out4[row * 16 + l16] = make_float4(2.0f * x0.x + acc.x,
                                           2.0f * x0.y + acc.y,
                                           2.0f * x0.z + acc.z,
                                           2.0f * x0.w + acc.w);
    }
}

// ---------------------------------------------------------------------------
// Inputs (metadata order): user_emb, item_emb, adj_row, adj_col, adj_vals,
//                          user_id, item_id. Output: 8192x64 float32.
// ---------------------------------------------------------------------------
extern "C" void kernel_launch(void* const* d_in, const int* in_sizes, int n_in,
                              void* d_out, int out_size) {
    const float* user_emb = (const float*)d_in[0];
    const float* item_emb = (const float*)d_in[1];
    const int4*  adj_row4 = (const int4*)d_in[2];
    const int*   adj_col  = (const int*)d_in[3];
    const float* adj_vals = (const float*)d_in[4];
    const int*   user_id  = (const int*)d_in[5];
    const int*   item_id  = (const int*)d_in[6];
    float4*      out4     = (float4*)d_out;

    k_init <<<64, 256>>>();
    k_build<<<(NSEL + 255) / 256, 256>>>(user_id, item_id);
    k_scan <<<SCAN_BLOCKS, 512>>>(adj_row4, adj_col, adj_vals,
                                  user_id, item_id);
    k_accum_out<<<NSEL / 8, 256>>>(user_emb, item_emb,
                                   user_id, item_id, out4);
}